// round 9
// baseline (speedup 1.0000x reference)
#include <cuda_runtime.h>
#include <cuda_fp16.h>
#include <stdint.h>

#define NG      2048
#define NH      1024          // folded grid length
#define MODES   512
#define MH      256           // modes per parity
#define RROWS   4096
#define SLD     40            // padded smem row stride (half); conflict-free ldmatrix
#define SLDA    136           // gemm3 A-tile row stride (half), [k][r] layout
#define SLDE    136           // epilogue cbuf stride (half)
#define STG_B   ((128 + 64) * SLD * 2)            // gemm1 stage bytes: 15360
#define STG3_B  (32 * SLDA * 2 + 64 * SLD * 2)    // gemm3 stage bytes: 13824
#define NSTG    4

// ---------------------------------------------------------------------------
// Static device scratch
// ---------------------------------------------------------------------------
__device__ float g_cosTab[2 * (NG - 1)];
__device__ __align__(16) __half g_B1e[MH * NH];        // [k2][n]  even fwd op, c[n] folded
__device__ __align__(16) __half g_B1o[MH * NH];        // [k2][n]  odd  fwd op
__device__ __align__(16) __half g_B3e[NH * MH];        // [n][k2]  even inv op, c[k] folded
__device__ __align__(16) __half g_B3o[NH * MH];        // [n][k2]  odd  inv op
__device__ __align__(16) __half g_Xe[RROWS * NH];      // [r][n]  x[n]+x[2047-n]
__device__ __align__(16) __half g_Xd[RROWS * NH];      // [r][n]  x[n]-x[2047-n]
__device__ __align__(16) __half g_C1h[MODES * RROWS];  // [pk][r] parity-major modes
__device__ __align__(16) __half g_Wt16[MODES * RROWS]; // [pk][i*64+o] parity-major
__device__ __align__(16) __half g_C2h[MODES * RROWS];  // [pk][r]

// ---------------------------------------------------------------------------
// Async-copy / MMA / ldmatrix helpers
// ---------------------------------------------------------------------------
__device__ __forceinline__ void cp_async16(void* smem, const void* gmem) {
    uint32_t s = (uint32_t)__cvta_generic_to_shared(smem);
    asm volatile("cp.async.cg.shared.global [%0], [%1], 16;\n" :: "r"(s), "l"(gmem));
}
#define CP_COMMIT() asm volatile("cp.async.commit_group;\n" ::: "memory")
#define CP_WAIT(n)  asm volatile("cp.async.wait_group %0;\n" :: "n"(n) : "memory")

#define MMA_F16(c, a, b)                                                        \
    asm volatile(                                                               \
        "mma.sync.aligned.m16n8k16.row.col.f32.f16.f16.f32 "                    \
        "{%0,%1,%2,%3},{%4,%5,%6,%7},{%8,%9},{%0,%1,%2,%3};\n"                  \
        : "+f"((c)[0]), "+f"((c)[1]), "+f"((c)[2]), "+f"((c)[3])                \
        : "r"((a)[0]), "r"((a)[1]), "r"((a)[2]), "r"((a)[3]),                   \
          "r"((b)[0]), "r"((b)[1]))

__device__ __forceinline__ void ldsm_x4(uint32_t& r0, uint32_t& r1, uint32_t& r2,
                                        uint32_t& r3, uint32_t saddr) {
    asm volatile("ldmatrix.sync.aligned.m8n8.x4.shared.b16 {%0,%1,%2,%3}, [%4];"
                 : "=r"(r0), "=r"(r1), "=r"(r2), "=r"(r3) : "r"(saddr));
}
__device__ __forceinline__ void ldsm_x4_t(uint32_t& r0, uint32_t& r1, uint32_t& r2,
                                          uint32_t& r3, uint32_t saddr) {
    asm volatile("ldmatrix.sync.aligned.m8n8.x4.trans.shared.b16 {%0,%1,%2,%3}, [%4];"
                 : "=r"(r0), "=r"(r1), "=r"(r2), "=r"(r3) : "r"(saddr));
}

// ---------------------------------------------------------------------------
// Init kernels
// ---------------------------------------------------------------------------
__global__ void init_table_kernel() {
    int i = blockIdx.x * blockDim.x + threadIdx.x;
    if (i < 2 * (NG - 1))
        g_cosTab[i] = cospif((float)i * (1.0f / (float)(NG - 1)));
}

__global__ void init_M_kernel() {
    int idx = blockIdx.x * blockDim.x + threadIdx.x;
    if (idx >= MH * NH) return;
    int k2 = idx >> 10, n = idx & (NH - 1);
    int ke = 2 * k2, ko = 2 * k2 + 1;
    float ve = g_cosTab[(ke * n) % (2 * (NG - 1))];
    float vo = g_cosTab[(ko * n) % (2 * (NG - 1))];
    float cn = (n == 0) ? 1.0f : 2.0f;
    g_B1e[idx] = __float2half(ve * cn);
    g_B1o[idx] = __float2half(vo * cn);
    float cke = (ke == 0) ? 1.0f : 2.0f;
    g_B3e[n * MH + k2] = __float2half(ve * cke);
    g_B3o[n * MH + k2] = __float2half(vo * 2.0f);
}

// e/d fold of X: e[r][n]=x[r][n]+x[r][2047-n], d=x-x  (n<1024), fp16
__global__ void convert_X_kernel(const float* __restrict__ x) {
    int idx = blockIdx.x * blockDim.x + threadIdx.x;
    if (idx >= RROWS * (NH / 4)) return;
    int r = idx >> 8;
    int n0 = (idx & 255) * 4;
    float4 fa = *(const float4*)&x[r * NG + n0];
    float4 fb = *(const float4*)&x[r * NG + (NG - 4 - n0)];
    float a[4] = {fa.x, fa.y, fa.z, fa.w};
    float b[4] = {fb.w, fb.z, fb.y, fb.x};
    union { __half h[4]; uint2 u; } pe, pd;
#pragma unroll
    for (int i = 0; i < 4; i++) {
        pe.h[i] = __float2half(a[i] + b[i]);
        pd.h[i] = __float2half(a[i] - b[i]);
    }
    *(uint2*)&g_Xe[r * NH + n0] = pe.u;
    *(uint2*)&g_Xd[r * NH + n0] = pd.u;
}

// transpose weights [i,o,k] f32 -> Wt16[pk][i*64+o] fp16, pk = (k&1)*256 + (k>>1)
// 64k x 128r tiles (256 blocks), 8 float4 loads + 8 uint4 stores per thread.
__global__ __launch_bounds__(256) void transpose_W_kernel(const float* __restrict__ w) {
    __shared__ float tile[64][129];   // [k][r]
    int kBase = blockIdx.x * 64;
    int rBase = blockIdx.y * 128;
    int tid = (int)threadIdx.x;
#pragma unroll
    for (int l = 0; l < 8; l++) {
        int idx = tid + l * 256;       // 2048 float4 = 128r x 16 kgroups
        int r = idx >> 4;              // 0..127
        int q = idx & 15;              // k-group of 4
        float4 v = *(const float4*)&w[(rBase + r) * MODES + kBase + q * 4];
        tile[q * 4 + 0][r] = v.x;
        tile[q * 4 + 1][r] = v.y;
        tile[q * 4 + 2][r] = v.z;
        tile[q * 4 + 3][r] = v.w;
    }
    __syncthreads();
#pragma unroll
    for (int l = 0; l < 4; l++) {
        int idx = tid + l * 256;       // 1024 uint4 = 64k x 16 rsegs
        int kk = idx >> 4;             // 0..63
        int seg = (idx & 15) * 8;      // 0..120
        int k = kBase + kk;
        int pk = (k & 1) * MH + (k >> 1);
        union { __half h[8]; uint4 u; } pkt;
#pragma unroll
        for (int c = 0; c < 8; c++) pkt.h[c] = __float2half(tile[kk][seg + c]);
        *(uint4*)&g_Wt16[pk * RROWS + rBase + seg] = pkt.u;
    }
}

// ---------------------------------------------------------------------------
// GEMM1 (folded): C1h[p*256+bn+kc][r] = sum_{n<1024} A_p[r][n] * B_p[k][n]
//   M=4096, N=256/parity, K=1024. CTA 128m x 64n, BK=32, 4-stage cp.async.
// ---------------------------------------------------------------------------
extern __shared__ __align__(16) unsigned char dsm[];

__global__ __launch_bounds__(256, 2) void gemm1_mma() {
    int tid = (int)threadIdx.x;
    int bm = blockIdx.y * 128;   // r
    int bn = blockIdx.x * 64;    // k2 within parity
    int p  = blockIdx.z;
    const __half* Asrc = p ? g_Xd : g_Xe;
    const __half* Bsrc = p ? g_B1o : g_B1e;

    int warp = tid >> 5, lane = tid & 31;
    int wm = warp >> 2, wn = warp & 3;
    int g = lane >> 2, t2 = (lane & 3) * 2;

    uint32_t sbase = (uint32_t)__cvta_generic_to_shared(dsm);

    int aRow[2], aSeg[2];
#pragma unroll
    for (int l = 0; l < 2; l++) {
        int idx = tid + l * 256;
        aRow[l] = idx >> 2;
        aSeg[l] = (idx & 3) * 8;
    }
    int bRow = tid >> 2, bSeg = (tid & 3) * 8;

    uint32_t aoff[4];
#pragma unroll
    for (int mi = 0; mi < 4; mi++)
        aoff[mi] = ((wm * 64 + mi * 16 + (lane & 15)) * SLD + ((lane >> 4) << 3)) * 2;
    uint32_t boff = (uint32_t)(128 * SLD * 2) +
                    ((wn * 16 + (lane & 7) + ((lane >> 4) << 3)) * SLD +
                     (((lane >> 3) & 1) << 3)) * 2;

    float acc[4][2][4];
#pragma unroll
    for (int a = 0; a < 4; a++)
#pragma unroll
        for (int b = 0; b < 2; b++)
#pragma unroll
            for (int c = 0; c < 4; c++) acc[a][b][c] = 0.0f;

    const int NIT = NH / 32;   // 32

#pragma unroll
    for (int s = 0; s < 3; s++) {
        __half* sA = (__half*)(dsm + s * STG_B);
        __half* sB = sA + 128 * SLD;
        int k0 = s * 32;
#pragma unroll
        for (int l = 0; l < 2; l++)
            cp_async16(&sA[aRow[l] * SLD + aSeg[l]], &Asrc[(bm + aRow[l]) * NH + k0 + aSeg[l]]);
        cp_async16(&sB[bRow * SLD + bSeg], &Bsrc[(bn + bRow) * NH + k0 + bSeg]);
        CP_COMMIT();
    }

    for (int it = 0; it < NIT; it++) {
        CP_WAIT(2);
        __syncthreads();
        if (it + 3 < NIT) {
            int s = (it + 3) & 3;
            int k0 = (it + 3) * 32;
            __half* sA = (__half*)(dsm + s * STG_B);
            __half* sB = sA + 128 * SLD;
#pragma unroll
            for (int l = 0; l < 2; l++)
                cp_async16(&sA[aRow[l] * SLD + aSeg[l]], &Asrc[(bm + aRow[l]) * NH + k0 + aSeg[l]]);
            cp_async16(&sB[bRow * SLD + bSeg], &Bsrc[(bn + bRow) * NH + k0 + bSeg]);
            CP_COMMIT();
        }
        uint32_t stg = sbase + (uint32_t)((it & 3) * STG_B);
#pragma unroll
        for (int ks = 0; ks < 2; ks++) {
            uint32_t kb = (uint32_t)(ks * 32);
            uint32_t a[4][4], b[2][2];
#pragma unroll
            for (int mi = 0; mi < 4; mi++)
                ldsm_x4(a[mi][0], a[mi][1], a[mi][2], a[mi][3], stg + aoff[mi] + kb);
            ldsm_x4(b[0][0], b[0][1], b[1][0], b[1][1], stg + boff + kb);
#pragma unroll
            for (int mi = 0; mi < 4; mi++)
#pragma unroll
                for (int ni = 0; ni < 2; ni++)
                    MMA_F16(acc[mi][ni], a[mi], b[ni]);
        }
    }
    __syncthreads();

    // Epilogue: stage transposed fp16 cbuf[k][r], coalesced write C1h (parity-major).
    __half* cbuf = (__half*)dsm;
#pragma unroll
    for (int mi = 0; mi < 4; mi++)
#pragma unroll
        for (int ni = 0; ni < 2; ni++) {
            int rl = wm * 64 + mi * 16 + g;
            int cl = wn * 16 + ni * 8 + t2;
            cbuf[cl * SLDE + rl]           = __float2half(acc[mi][ni][0]);
            cbuf[(cl + 1) * SLDE + rl]     = __float2half(acc[mi][ni][1]);
            cbuf[cl * SLDE + rl + 8]       = __float2half(acc[mi][ni][2]);
            cbuf[(cl + 1) * SLDE + rl + 8] = __float2half(acc[mi][ni][3]);
        }
    __syncthreads();
    int kgBase = p * MH + bn;
#pragma unroll
    for (int q = 0; q < 8; q++) {
        int idx = tid + q * 256;
        int kc = idx >> 5;
        int seg = (idx & 31) * 4;
        *(uint2*)&g_C1h[(kgBase + kc) * RROWS + bm + seg] = *(uint2*)&cbuf[kc * SLDE + seg];
    }
}

// ---------------------------------------------------------------------------
// Mix (tensor cores): per pk, C2h[pk][b*64+o] = sum_i C1h[pk][b*64+i]*Wt16[pk][i][o]
// ---------------------------------------------------------------------------
__global__ __launch_bounds__(128) void mix_mma_kernel() {
    int k = blockIdx.x;
    __shared__ __align__(16) __half sA[64][72];
    __shared__ __align__(16) __half sW[64][72];
    const __half* a = &g_C1h[k * RROWS];
    const __half* w = &g_Wt16[k * RROWS];
    int tid = (int)threadIdx.x;
#pragma unroll
    for (int l = 0; l < 4; l++) {
        int idx = tid + l * 128;
        int r = idx >> 3, seg = (idx & 7) * 8;
        *(uint4*)&sA[r][seg] = *(const uint4*)&a[r * 64 + seg];
        *(uint4*)&sW[r][seg] = *(const uint4*)&w[r * 64 + seg];
    }
    __syncthreads();

    int warp = tid >> 5, lane = tid & 31;
    int g = lane >> 2, t2 = (lane & 3) * 2;
    uint32_t sAb = (uint32_t)__cvta_generic_to_shared(&sA[0][0]);
    uint32_t sWb = (uint32_t)__cvta_generic_to_shared(&sW[0][0]);

    float acc[8][4];
#pragma unroll
    for (int i = 0; i < 8; i++)
#pragma unroll
        for (int j = 0; j < 4; j++) acc[i][j] = 0.0f;

#pragma unroll
    for (int ks = 0; ks < 4; ks++) {
        uint32_t av[4];
        uint32_t aaddr = sAb + ((warp * 16 + (lane & 15)) * 72 + ks * 16 + ((lane >> 4) << 3)) * 2;
        ldsm_x4(av[0], av[1], av[2], av[3], aaddr);
#pragma unroll
        for (int nq = 0; nq < 4; nq++) {
            uint32_t b0, b1, b2, b3;
            uint32_t baddr = sWb + ((ks * 16 + (lane & 15)) * 72 + nq * 16 + ((lane >> 4) << 3)) * 2;
            ldsm_x4_t(b0, b1, b2, b3, baddr);
            uint32_t bb0[2] = {b0, b1}, bb1[2] = {b2, b3};
            MMA_F16(acc[nq * 2], av, bb0);
            MMA_F16(acc[nq * 2 + 1], av, bb1);
        }
    }

    __half* c2 = &g_C2h[k * RROWS];
#pragma unroll
    for (int ni = 0; ni < 8; ni++) {
        int col = ni * 8 + t2;
        __half2 v0 = __floats2half2_rn(acc[ni][0], acc[ni][1]);
        __half2 v1 = __floats2half2_rn(acc[ni][2], acc[ni][3]);
        *(__half2*)&c2[(warp * 16 + g) * 64 + col]     = v0;
        *(__half2*)&c2[(warp * 16 + g + 8) * 64 + col] = v1;
    }
}

// ---------------------------------------------------------------------------
// GEMM3 (folded + butterfly), A direct from C2h[pk][r] via ldmatrix.trans.
//   Single barrier per iteration (gemm1 schedule).
// ---------------------------------------------------------------------------
__global__ __launch_bounds__(256, 2) void gemm3_mma(float* __restrict__ out) {
    int tid = (int)threadIdx.x;
    int bm = blockIdx.y * 128;   // r
    int bn = blockIdx.x * 64;    // n (folded half)
    int warp = tid >> 5, lane = tid & 31;
    int wm = warp >> 2, wn = warp & 3;
    int g = lane >> 2, t2 = (lane & 3) * 2;

    uint32_t sbase = (uint32_t)__cvta_generic_to_shared(dsm);

    int aRow[2], aSeg[2];
#pragma unroll
    for (int l = 0; l < 2; l++) {
        int idx = tid + l * 256;
        aRow[l] = idx >> 4;
        aSeg[l] = (idx & 15) * 8;
    }
    int bRow = tid >> 2, bSeg = (tid & 3) * 8;

    uint32_t atoff[4];
#pragma unroll
    for (int mi = 0; mi < 4; mi++)
        atoff[mi] = (((((lane >> 4) & 1) * 8 + (lane & 7)) * SLDA) +
                     wm * 64 + mi * 16 + (((lane >> 3) & 1) * 8)) * 2;
    uint32_t boff = (uint32_t)(32 * SLDA * 2) +
                    ((wn * 16 + (lane & 7) + ((lane >> 4) << 3)) * SLD +
                     (((lane >> 3) & 1) << 3)) * 2;

    float acc_e[4][2][4], acc_o[4][2][4];
#pragma unroll
    for (int a = 0; a < 4; a++)
#pragma unroll
        for (int b = 0; b < 2; b++)
#pragma unroll
            for (int c = 0; c < 4; c++) { acc_e[a][b][c] = 0.0f; acc_o[a][b][c] = 0.0f; }

#define G3_LOAD(j)                                                                   \
    do {                                                                             \
        int s_ = (j) & 3;                                                            \
        int ph_ = (j) >> 3;                                                          \
        int kk_ = ((j) & 7) * 32;                                                    \
        __half* sA_ = (__half*)(dsm + s_ * STG3_B);                                  \
        __half* sB_ = (__half*)(dsm + s_ * STG3_B + 32 * SLDA * 2);                  \
        const __half* Bs_ = ph_ ? g_B3o : g_B3e;                                     \
        _Pragma("unroll")                                                            \
        for (int l_ = 0; l_ < 2; l_++)                                               \
            cp_async16(&sA_[aRow[l_] * SLDA + aSeg[l_]],                             \
                       &g_C2h[(ph_ * MH + kk_ + aRow[l_]) * RROWS + bm + aSeg[l_]]); \
        cp_async16(&sB_[bRow * SLD + bSeg], &Bs_[(bn + bRow) * MH + kk_ + bSeg]);    \
        CP_COMMIT();                                                                 \
    } while (0)

#define G3_COMPUTE(j, ACC)                                                           \
    do {                                                                             \
        uint32_t stg_ = sbase + (uint32_t)(((j) & 3) * STG3_B);                      \
        _Pragma("unroll")                                                            \
        for (int ks_ = 0; ks_ < 2; ks_++) {                                          \
            uint32_t ka_ = (uint32_t)(ks_ * 16 * SLDA * 2);                          \
            uint32_t kb_ = (uint32_t)(ks_ * 32);                                     \
            uint32_t a_[4][4], b_[2][2];                                             \
            _Pragma("unroll")                                                        \
            for (int mi_ = 0; mi_ < 4; mi_++)                                        \
                ldsm_x4_t(a_[mi_][0], a_[mi_][1], a_[mi_][2], a_[mi_][3],            \
                          stg_ + atoff[mi_] + ka_);                                  \
            ldsm_x4(b_[0][0], b_[0][1], b_[1][0], b_[1][1], stg_ + boff + kb_);      \
            _Pragma("unroll")                                                        \
            for (int mi_ = 0; mi_ < 4; mi_++)                                        \
                _Pragma("unroll")                                                    \
                for (int ni_ = 0; ni_ < 2; ni_++)                                    \
                    MMA_F16(ACC[mi_][ni_], a_[mi_], b_[ni_]);                        \
        }                                                                            \
    } while (0)

#pragma unroll
    for (int s = 0; s < 3; s++) G3_LOAD(s);

    for (int j = 0; j < 8; j++) {
        CP_WAIT(2);
        __syncthreads();
        G3_LOAD(j + 3);
        G3_COMPUTE(j, acc_e);
    }
    for (int j = 8; j < 16; j++) {
        CP_WAIT(2);
        __syncthreads();
        if (j + 3 < 16) G3_LOAD(j + 3);
        G3_COMPUTE(j, acc_o);
    }

#pragma unroll
    for (int mi = 0; mi < 4; mi++)
#pragma unroll
        for (int ni = 0; ni < 2; ni++) {
            int row = bm + wm * 64 + mi * 16 + g;
            int col = bn + wn * 16 + ni * 8 + t2;
            float e0 = acc_e[mi][ni][0], e1 = acc_e[mi][ni][1];
            float e2 = acc_e[mi][ni][2], e3 = acc_e[mi][ni][3];
            float o0 = acc_o[mi][ni][0], o1 = acc_o[mi][ni][1];
            float o2 = acc_o[mi][ni][2], o3 = acc_o[mi][ni][3];
            *(float2*)&out[row * NG + col]       = make_float2(e0 + o0, e1 + o1);
            *(float2*)&out[(row + 8) * NG + col] = make_float2(e2 + o2, e3 + o3);
            int mcol = NG - 2 - col;
            *(float2*)&out[row * NG + mcol]       = make_float2(e1 - o1, e0 - o0);
            *(float2*)&out[(row + 8) * NG + mcol] = make_float2(e3 - o3, e2 - o2);
        }
}

// ---------------------------------------------------------------------------
// Launch
// ---------------------------------------------------------------------------
extern "C" void kernel_launch(void* const* d_in, const int* in_sizes, int n_in,
                              void* d_out, int out_size) {
    const float* x = (const float*)d_in[0];   // [64, 64, 2048] f32
    const float* w = (const float*)d_in[1];   // [64, 64, 512]  f32
    float* out = (float*)d_out;               // [64, 64, 2048] f32

    cudaFuncSetAttribute(gemm1_mma, cudaFuncAttributeMaxDynamicSharedMemorySize, NSTG * STG_B);
    cudaFuncSetAttribute(gemm3_mma, cudaFuncAttributeMaxDynamicSharedMemorySize, NSTG * STG3_B);

    init_table_kernel<<<16, 256>>>();
    init_M_kernel<<<(MH * NH + 255) / 256, 256>>>();
    convert_X_kernel<<<(RROWS * (NH / 4) + 255) / 256, 256>>>(x);
    transpose_W_kernel<<<dim3(MODES / 64, RROWS / 128), 256>>>(w);
    gemm1_mma<<<dim3(MH / 64, RROWS / 128, 2), 256, NSTG * STG_B>>>();
    mix_mma_kernel<<<MODES, 128>>>();
    gemm3_mma<<<dim3(NH / 64, RROWS / 128), 256, NSTG * STG3_B>>>(out);
}

// round 10
// speedup vs baseline: 1.1355x; 1.1355x over previous
#include <cuda_runtime.h>
#include <cuda_fp16.h>
#include <stdint.h>

#define NG      2048
#define NH      1024          // folded grid length
#define MODES   512
#define MH      256           // modes per parity
#define RROWS   4096
#define SLD     40            // padded smem row stride (half); conflict-free ldmatrix
#define SLDA    136           // gemm3 A-tile row stride (half), [k][r] layout
#define SLDE    136           // epilogue cbuf stride (half)
#define STG_B   ((128 + 64) * SLD * 2)            // gemm1 stage bytes: 15360
#define STG3_B  (32 * SLDA * 2 + 64 * SLD * 2)    // gemm3 stage bytes: 13824
#define NSTG    4

// prep_kernel block ranges
#define PREP_CVT   4096                       // convert_X blocks
#define PREP_TRW   (PREP_CVT + 1024)          // transpose_W blocks
#define PREP_TOT   (PREP_TRW + 1024)          // init_M blocks

// ---------------------------------------------------------------------------
// Static device scratch
// ---------------------------------------------------------------------------
__device__ __align__(16) __half g_B1e[MH * NH];        // [k2][n]  even fwd op, c[n] folded
__device__ __align__(16) __half g_B1o[MH * NH];        // [k2][n]  odd  fwd op
__device__ __align__(16) __half g_B3e[NH * MH];        // [n][k2]  even inv op, c[k] folded
__device__ __align__(16) __half g_B3o[NH * MH];        // [n][k2]  odd  inv op
__device__ __align__(16) __half g_Xe[RROWS * NH];      // [r][n]  x[n]+x[2047-n]
__device__ __align__(16) __half g_Xd[RROWS * NH];      // [r][n]  x[n]-x[2047-n]
__device__ __align__(16) __half g_C1h[MODES * RROWS];  // [pk][r] parity-major modes
__device__ __align__(16) __half g_Wt16[MODES * RROWS]; // [pk][i*64+o] parity-major
__device__ __align__(16) __half g_C2h[MODES * RROWS];  // [pk][r]

// ---------------------------------------------------------------------------
// Async-copy / MMA / ldmatrix helpers
// ---------------------------------------------------------------------------
__device__ __forceinline__ void cp_async16(void* smem, const void* gmem) {
    uint32_t s = (uint32_t)__cvta_generic_to_shared(smem);
    asm volatile("cp.async.cg.shared.global [%0], [%1], 16;\n" :: "r"(s), "l"(gmem));
}
#define CP_COMMIT() asm volatile("cp.async.commit_group;\n" ::: "memory")
#define CP_WAIT(n)  asm volatile("cp.async.wait_group %0;\n" :: "n"(n) : "memory")

#define MMA_F16(c, a, b)                                                        \
    asm volatile(                                                               \
        "mma.sync.aligned.m16n8k16.row.col.f32.f16.f16.f32 "                    \
        "{%0,%1,%2,%3},{%4,%5,%6,%7},{%8,%9},{%0,%1,%2,%3};\n"                  \
        : "+f"((c)[0]), "+f"((c)[1]), "+f"((c)[2]), "+f"((c)[3])                \
        : "r"((a)[0]), "r"((a)[1]), "r"((a)[2]), "r"((a)[3]),                   \
          "r"((b)[0]), "r"((b)[1]))

__device__ __forceinline__ void ldsm_x4(uint32_t& r0, uint32_t& r1, uint32_t& r2,
                                        uint32_t& r3, uint32_t saddr) {
    asm volatile("ldmatrix.sync.aligned.m8n8.x4.shared.b16 {%0,%1,%2,%3}, [%4];"
                 : "=r"(r0), "=r"(r1), "=r"(r2), "=r"(r3) : "r"(saddr));
}
__device__ __forceinline__ void ldsm_x4_t(uint32_t& r0, uint32_t& r1, uint32_t& r2,
                                          uint32_t& r3, uint32_t saddr) {
    asm volatile("ldmatrix.sync.aligned.m8n8.x4.trans.shared.b16 {%0,%1,%2,%3}, [%4];"
                 : "=r"(r0), "=r"(r1), "=r"(r2), "=r"(r3) : "r"(saddr));
}

// ---------------------------------------------------------------------------
// Fused prologue: convert_X | transpose_W | init_M in one launch.
//   blocks [0, 4096)      : X e/d fold -> fp16
//   blocks [4096, 5120)   : W transpose -> Wt16 (parity-major)
//   blocks [5120, 6144)   : DCT operator build (direct cospif)
// ---------------------------------------------------------------------------
__global__ __launch_bounds__(256) void prep_kernel(const float* __restrict__ x,
                                                   const float* __restrict__ w) {
    __shared__ float tile[64][33];   // used by transpose_W branch only
    int blk = (int)blockIdx.x;
    int tid = (int)threadIdx.x;

    if (blk < PREP_CVT) {
        // ---- convert_X: e/d fold, fp16 ----
        int idx = blk * 256 + tid;
        int r = idx >> 8;
        int n0 = (idx & 255) * 4;
        float4 fa = *(const float4*)&x[r * NG + n0];
        float4 fb = *(const float4*)&x[r * NG + (NG - 4 - n0)];
        float a[4] = {fa.x, fa.y, fa.z, fa.w};
        float b[4] = {fb.w, fb.z, fb.y, fb.x};
        union { __half h[4]; uint2 u; } pe, pd;
#pragma unroll
        for (int i = 0; i < 4; i++) {
            pe.h[i] = __float2half(a[i] + b[i]);
            pd.h[i] = __float2half(a[i] - b[i]);
        }
        *(uint2*)&g_Xe[r * NH + n0] = pe.u;
        *(uint2*)&g_Xd[r * NH + n0] = pd.u;
    } else if (blk < PREP_TRW) {
        // ---- transpose_W: [i,o,k] f32 -> Wt16[pk][r] fp16 (64k x 32r tiles) ----
        int b2 = blk - PREP_CVT;          // 0..1023
        int kBase = (b2 & 7) * 64;        // 8 k-tiles
        int rBase = (b2 >> 3) * 32;       // 128 r-tiles
#pragma unroll
        for (int l = 0; l < 2; l++) {
            int idx = tid + l * 256;
            int r = idx >> 4;             // 0..31
            int q = idx & 15;             // k-group of 4
            float4 v = *(const float4*)&w[(rBase + r) * MODES + kBase + q * 4];
            tile[q * 4 + 0][r] = v.x;
            tile[q * 4 + 1][r] = v.y;
            tile[q * 4 + 2][r] = v.z;
            tile[q * 4 + 3][r] = v.w;
        }
        __syncthreads();
        {
            int kk = tid >> 2;            // 0..63
            int seg = (tid & 3) * 8;      // 0,8,16,24
            int k = kBase + kk;
            int pk = (k & 1) * MH + (k >> 1);
            union { __half h[8]; uint4 u; } pkt;
#pragma unroll
            for (int c = 0; c < 8; c++) pkt.h[c] = __float2half(tile[kk][seg + c]);
            *(uint4*)&g_Wt16[pk * RROWS + rBase + seg] = pkt.u;
        }
    } else {
        // ---- init_M: folded DCT-I operators, direct cospif ----
        int idx = (blk - PREP_TRW) * 256 + tid;   // 0 .. MH*NH-1
        int k2 = idx >> 10, n = idx & (NH - 1);
        int ke = 2 * k2, ko = 2 * k2 + 1;
        const float inv = 1.0f / (float)(NG - 1);
        float ve = cospif((float)((ke * n) % (2 * (NG - 1))) * inv);
        float vo = cospif((float)((ko * n) % (2 * (NG - 1))) * inv);
        float cn = (n == 0) ? 1.0f : 2.0f;
        g_B1e[idx] = __float2half(ve * cn);
        g_B1o[idx] = __float2half(vo * cn);
        float cke = (ke == 0) ? 1.0f : 2.0f;
        g_B3e[n * MH + k2] = __float2half(ve * cke);
        g_B3o[n * MH + k2] = __float2half(vo * 2.0f);
    }
}

// ---------------------------------------------------------------------------
// GEMM1 (folded): C1h[p*256+bn+kc][r] = sum_{n<1024} A_p[r][n] * B_p[k][n]
//   M=4096, N=256/parity, K=1024. CTA 128m x 64n, BK=32, 4-stage cp.async.
// ---------------------------------------------------------------------------
extern __shared__ __align__(16) unsigned char dsm[];

__global__ __launch_bounds__(256, 2) void gemm1_mma() {
    int tid = (int)threadIdx.x;
    int bm = blockIdx.y * 128;   // r
    int bn = blockIdx.x * 64;    // k2 within parity
    int p  = blockIdx.z;
    const __half* Asrc = p ? g_Xd : g_Xe;
    const __half* Bsrc = p ? g_B1o : g_B1e;

    int warp = tid >> 5, lane = tid & 31;
    int wm = warp >> 2, wn = warp & 3;
    int g = lane >> 2, t2 = (lane & 3) * 2;

    uint32_t sbase = (uint32_t)__cvta_generic_to_shared(dsm);

    int aRow[2], aSeg[2];
#pragma unroll
    for (int l = 0; l < 2; l++) {
        int idx = tid + l * 256;
        aRow[l] = idx >> 2;
        aSeg[l] = (idx & 3) * 8;
    }
    int bRow = tid >> 2, bSeg = (tid & 3) * 8;

    uint32_t aoff[4];
#pragma unroll
    for (int mi = 0; mi < 4; mi++)
        aoff[mi] = ((wm * 64 + mi * 16 + (lane & 15)) * SLD + ((lane >> 4) << 3)) * 2;
    uint32_t boff = (uint32_t)(128 * SLD * 2) +
                    ((wn * 16 + (lane & 7) + ((lane >> 4) << 3)) * SLD +
                     (((lane >> 3) & 1) << 3)) * 2;

    float acc[4][2][4];
#pragma unroll
    for (int a = 0; a < 4; a++)
#pragma unroll
        for (int b = 0; b < 2; b++)
#pragma unroll
            for (int c = 0; c < 4; c++) acc[a][b][c] = 0.0f;

    const int NIT = NH / 32;   // 32

#pragma unroll
    for (int s = 0; s < 3; s++) {
        __half* sA = (__half*)(dsm + s * STG_B);
        __half* sB = sA + 128 * SLD;
        int k0 = s * 32;
#pragma unroll
        for (int l = 0; l < 2; l++)
            cp_async16(&sA[aRow[l] * SLD + aSeg[l]], &Asrc[(bm + aRow[l]) * NH + k0 + aSeg[l]]);
        cp_async16(&sB[bRow * SLD + bSeg], &Bsrc[(bn + bRow) * NH + k0 + bSeg]);
        CP_COMMIT();
    }

    for (int it = 0; it < NIT; it++) {
        CP_WAIT(2);
        __syncthreads();
        if (it + 3 < NIT) {
            int s = (it + 3) & 3;
            int k0 = (it + 3) * 32;
            __half* sA = (__half*)(dsm + s * STG_B);
            __half* sB = sA + 128 * SLD;
#pragma unroll
            for (int l = 0; l < 2; l++)
                cp_async16(&sA[aRow[l] * SLD + aSeg[l]], &Asrc[(bm + aRow[l]) * NH + k0 + aSeg[l]]);
            cp_async16(&sB[bRow * SLD + bSeg], &Bsrc[(bn + bRow) * NH + k0 + bSeg]);
            CP_COMMIT();
        }
        uint32_t stg = sbase + (uint32_t)((it & 3) * STG_B);
#pragma unroll
        for (int ks = 0; ks < 2; ks++) {
            uint32_t kb = (uint32_t)(ks * 32);
            uint32_t a[4][4], b[2][2];
#pragma unroll
            for (int mi = 0; mi < 4; mi++)
                ldsm_x4(a[mi][0], a[mi][1], a[mi][2], a[mi][3], stg + aoff[mi] + kb);
            ldsm_x4(b[0][0], b[0][1], b[1][0], b[1][1], stg + boff + kb);
#pragma unroll
            for (int mi = 0; mi < 4; mi++)
#pragma unroll
                for (int ni = 0; ni < 2; ni++)
                    MMA_F16(acc[mi][ni], a[mi], b[ni]);
        }
    }
    __syncthreads();

    // Epilogue: stage transposed fp16 cbuf[k][r], coalesced write C1h (parity-major).
    __half* cbuf = (__half*)dsm;
#pragma unroll
    for (int mi = 0; mi < 4; mi++)
#pragma unroll
        for (int ni = 0; ni < 2; ni++) {
            int rl = wm * 64 + mi * 16 + g;
            int cl = wn * 16 + ni * 8 + t2;
            cbuf[cl * SLDE + rl]           = __float2half(acc[mi][ni][0]);
            cbuf[(cl + 1) * SLDE + rl]     = __float2half(acc[mi][ni][1]);
            cbuf[cl * SLDE + rl + 8]       = __float2half(acc[mi][ni][2]);
            cbuf[(cl + 1) * SLDE + rl + 8] = __float2half(acc[mi][ni][3]);
        }
    __syncthreads();
    int kgBase = p * MH + bn;
#pragma unroll
    for (int q = 0; q < 8; q++) {
        int idx = tid + q * 256;
        int kc = idx >> 5;
        int seg = (idx & 31) * 4;
        *(uint2*)&g_C1h[(kgBase + kc) * RROWS + bm + seg] = *(uint2*)&cbuf[kc * SLDE + seg];
    }
}

// ---------------------------------------------------------------------------
// Mix (tensor cores): per pk, C2h[pk][b*64+o] = sum_i C1h[pk][b*64+i]*Wt16[pk][i][o]
// ---------------------------------------------------------------------------
__global__ __launch_bounds__(128) void mix_mma_kernel() {
    int k = blockIdx.x;
    __shared__ __align__(16) __half sA[64][72];
    __shared__ __align__(16) __half sW[64][72];
    const __half* a = &g_C1h[k * RROWS];
    const __half* w = &g_Wt16[k * RROWS];
    int tid = (int)threadIdx.x;
#pragma unroll
    for (int l = 0; l < 4; l++) {
        int idx = tid + l * 128;
        int r = idx >> 3, seg = (idx & 7) * 8;
        *(uint4*)&sA[r][seg] = *(const uint4*)&a[r * 64 + seg];
        *(uint4*)&sW[r][seg] = *(const uint4*)&w[r * 64 + seg];
    }
    __syncthreads();

    int warp = tid >> 5, lane = tid & 31;
    int g = lane >> 2, t2 = (lane & 3) * 2;
    uint32_t sAb = (uint32_t)__cvta_generic_to_shared(&sA[0][0]);
    uint32_t sWb = (uint32_t)__cvta_generic_to_shared(&sW[0][0]);

    float acc[8][4];
#pragma unroll
    for (int i = 0; i < 8; i++)
#pragma unroll
        for (int j = 0; j < 4; j++) acc[i][j] = 0.0f;

#pragma unroll
    for (int ks = 0; ks < 4; ks++) {
        uint32_t av[4];
        uint32_t aaddr = sAb + ((warp * 16 + (lane & 15)) * 72 + ks * 16 + ((lane >> 4) << 3)) * 2;
        ldsm_x4(av[0], av[1], av[2], av[3], aaddr);
#pragma unroll
        for (int nq = 0; nq < 4; nq++) {
            uint32_t b0, b1, b2, b3;
            uint32_t baddr = sWb + ((ks * 16 + (lane & 15)) * 72 + nq * 16 + ((lane >> 4) << 3)) * 2;
            ldsm_x4_t(b0, b1, b2, b3, baddr);
            uint32_t bb0[2] = {b0, b1}, bb1[2] = {b2, b3};
            MMA_F16(acc[nq * 2], av, bb0);
            MMA_F16(acc[nq * 2 + 1], av, bb1);
        }
    }

    __half* c2 = &g_C2h[k * RROWS];
#pragma unroll
    for (int ni = 0; ni < 8; ni++) {
        int col = ni * 8 + t2;
        __half2 v0 = __floats2half2_rn(acc[ni][0], acc[ni][1]);
        __half2 v1 = __floats2half2_rn(acc[ni][2], acc[ni][3]);
        *(__half2*)&c2[(warp * 16 + g) * 64 + col]     = v0;
        *(__half2*)&c2[(warp * 16 + g + 8) * 64 + col] = v1;
    }
}

// ---------------------------------------------------------------------------
// GEMM3 (folded + butterfly), A direct from C2h[pk][r] via ldmatrix.trans.
// ---------------------------------------------------------------------------
__global__ __launch_bounds__(256, 2) void gemm3_mma(float* __restrict__ out) {
    int tid = (int)threadIdx.x;
    int bm = blockIdx.y * 128;   // r
    int bn = blockIdx.x * 64;    // n (folded half)
    int warp = tid >> 5, lane = tid & 31;
    int wm = warp >> 2, wn = warp & 3;
    int g = lane >> 2, t2 = (lane & 3) * 2;

    uint32_t sbase = (uint32_t)__cvta_generic_to_shared(dsm);

    int aRow[2], aSeg[2];
#pragma unroll
    for (int l = 0; l < 2; l++) {
        int idx = tid + l * 256;
        aRow[l] = idx >> 4;
        aSeg[l] = (idx & 15) * 8;
    }
    int bRow = tid >> 2, bSeg = (tid & 3) * 8;

    uint32_t atoff[4];
#pragma unroll
    for (int mi = 0; mi < 4; mi++)
        atoff[mi] = (((((lane >> 4) & 1) * 8 + (lane & 7)) * SLDA) +
                     wm * 64 + mi * 16 + (((lane >> 3) & 1) * 8)) * 2;
    uint32_t boff = (uint32_t)(32 * SLDA * 2) +
                    ((wn * 16 + (lane & 7) + ((lane >> 4) << 3)) * SLD +
                     (((lane >> 3) & 1) << 3)) * 2;

    float acc_e[4][2][4], acc_o[4][2][4];
#pragma unroll
    for (int a = 0; a < 4; a++)
#pragma unroll
        for (int b = 0; b < 2; b++)
#pragma unroll
            for (int c = 0; c < 4; c++) { acc_e[a][b][c] = 0.0f; acc_o[a][b][c] = 0.0f; }

#define G3_LOAD(j)                                                                   \
    do {                                                                             \
        int s_ = (j) & 3;                                                            \
        int ph_ = (j) >> 3;                                                          \
        int kk_ = ((j) & 7) * 32;                                                    \
        __half* sA_ = (__half*)(dsm + s_ * STG3_B);                                  \
        __half* sB_ = (__half*)(dsm + s_ * STG3_B + 32 * SLDA * 2);                  \
        const __half* Bs_ = ph_ ? g_B3o : g_B3e;                                     \
        _Pragma("unroll")                                                            \
        for (int l_ = 0; l_ < 2; l_++)                                               \
            cp_async16(&sA_[aRow[l_] * SLDA + aSeg[l_]],                             \
                       &g_C2h[(ph_ * MH + kk_ + aRow[l_]) * RROWS + bm + aSeg[l_]]); \
        cp_async16(&sB_[bRow * SLD + bSeg], &Bs_[(bn + bRow) * MH + kk_ + bSeg]);    \
        CP_COMMIT();                                                                 \
    } while (0)

#define G3_COMPUTE(j, ACC)                                                           \
    do {                                                                             \
        uint32_t stg_ = sbase + (uint32_t)(((j) & 3) * STG3_B);                      \
        _Pragma("unroll")                                                            \
        for (int ks_ = 0; ks_ < 2; ks_++) {                                          \
            uint32_t ka_ = (uint32_t)(ks_ * 16 * SLDA * 2);                          \
            uint32_t kb_ = (uint32_t)(ks_ * 32);                                     \
            uint32_t a_[4][4], b_[2][2];                                             \
            _Pragma("unroll")                                                        \
            for (int mi_ = 0; mi_ < 4; mi_++)                                        \
                ldsm_x4_t(a_[mi_][0], a_[mi_][1], a_[mi_][2], a_[mi_][3],            \
                          stg_ + atoff[mi_] + ka_);                                  \
            ldsm_x4(b_[0][0], b_[0][1], b_[1][0], b_[1][1], stg_ + boff + kb_);      \
            _Pragma("unroll")                                                        \
            for (int mi_ = 0; mi_ < 4; mi_++)                                        \
                _Pragma("unroll")                                                    \
                for (int ni_ = 0; ni_ < 2; ni_++)                                    \
                    MMA_F16(ACC[mi_][ni_], a_[mi_], b_[ni_]);                        \
        }                                                                            \
    } while (0)

#pragma unroll
    for (int s = 0; s < 3; s++) G3_LOAD(s);

    for (int j = 0; j < 8; j++) {
        CP_WAIT(2);
        __syncthreads();
        G3_LOAD(j + 3);
        G3_COMPUTE(j, acc_e);
        __syncthreads();
    }
    for (int j = 8; j < 16; j++) {
        CP_WAIT(2);
        __syncthreads();
        if (j + 3 < 16) G3_LOAD(j + 3);
        G3_COMPUTE(j, acc_o);
        __syncthreads();
    }

#pragma unroll
    for (int mi = 0; mi < 4; mi++)
#pragma unroll
        for (int ni = 0; ni < 2; ni++) {
            int row = bm + wm * 64 + mi * 16 + g;
            int col = bn + wn * 16 + ni * 8 + t2;
            float e0 = acc_e[mi][ni][0], e1 = acc_e[mi][ni][1];
            float e2 = acc_e[mi][ni][2], e3 = acc_e[mi][ni][3];
            float o0 = acc_o[mi][ni][0], o1 = acc_o[mi][ni][1];
            float o2 = acc_o[mi][ni][2], o3 = acc_o[mi][ni][3];
            *(float2*)&out[row * NG + col]       = make_float2(e0 + o0, e1 + o1);
            *(float2*)&out[(row + 8) * NG + col] = make_float2(e2 + o2, e3 + o3);
            int mcol = NG - 2 - col;
            *(float2*)&out[row * NG + mcol]       = make_float2(e1 - o1, e0 - o0);
            *(float2*)&out[(row + 8) * NG + mcol] = make_float2(e3 - o3, e2 - o2);
        }
}

// ---------------------------------------------------------------------------
// Launch
// ---------------------------------------------------------------------------
extern "C" void kernel_launch(void* const* d_in, const int* in_sizes, int n_in,
                              void* d_out, int out_size) {
    const float* x = (const float*)d_in[0];   // [64, 64, 2048] f32
    const float* w = (const float*)d_in[1];   // [64, 64, 512]  f32
    float* out = (float*)d_out;               // [64, 64, 2048] f32

    cudaFuncSetAttribute(gemm1_mma, cudaFuncAttributeMaxDynamicSharedMemorySize, NSTG * STG_B);
    cudaFuncSetAttribute(gemm3_mma, cudaFuncAttributeMaxDynamicSharedMemorySize, NSTG * STG3_B);

    prep_kernel<<<PREP_TOT, 256>>>(x, w);
    gemm1_mma<<<dim3(MH / 64, RROWS / 128, 2), 256, NSTG * STG_B>>>();
    mix_mma_kernel<<<MODES, 128>>>();
    gemm3_mma<<<dim3(NH / 64, RROWS / 128), 256, NSTG * STG3_B>>>(out);
}

// round 11
// speedup vs baseline: 1.1804x; 1.0396x over previous
#include <cuda_runtime.h>
#include <cuda_fp16.h>
#include <stdint.h>

#define NG      2048
#define NH      1024          // folded grid length
#define MODES   512
#define MH      256           // modes per parity
#define RROWS   4096
#define SLD1    72            // [r][k]/[n][k] smem row stride for BK=64 (halves)
#define SLDA    136           // gemm3 A-tile row stride (half), [k][r] layout
#define SLDE    136           // epilogue cbuf stride (half)
#define STG_B   ((128 + 64) * SLD1 * 2)           // gemm1 stage bytes: 27648
#define STG3_B  (64 * SLDA * 2 + 64 * SLD1 * 2)   // gemm3 stage bytes: 26624
#define NSTG    3

// prep_kernel block ranges
#define PREP_CVT   4096                       // convert_X blocks
#define PREP_TRW   (PREP_CVT + 1024)          // transpose_W blocks
#define PREP_TOT   (PREP_TRW + 1024)          // init_M blocks

// ---------------------------------------------------------------------------
// Static device scratch
// ---------------------------------------------------------------------------
__device__ __align__(16) __half g_B1e[MH * NH];        // [k2][n]  even fwd op, c[n] folded
__device__ __align__(16) __half g_B1o[MH * NH];        // [k2][n]  odd  fwd op
__device__ __align__(16) __half g_B3e[NH * MH];        // [n][k2]  even inv op, c[k] folded
__device__ __align__(16) __half g_B3o[NH * MH];        // [n][k2]  odd  inv op
__device__ __align__(16) __half g_Xe[RROWS * NH];      // [r][n]  x[n]+x[2047-n]
__device__ __align__(16) __half g_Xd[RROWS * NH];      // [r][n]  x[n]-x[2047-n]
__device__ __align__(16) __half g_C1h[MODES * RROWS];  // [pk][r] parity-major modes
__device__ __align__(16) __half g_Wt16[MODES * RROWS]; // [pk][i*64+o] parity-major
__device__ __align__(16) __half g_C2h[MODES * RROWS];  // [pk][r]

// ---------------------------------------------------------------------------
// Async-copy / MMA / ldmatrix helpers
// ---------------------------------------------------------------------------
__device__ __forceinline__ void cp_async16(void* smem, const void* gmem) {
    uint32_t s = (uint32_t)__cvta_generic_to_shared(smem);
    asm volatile("cp.async.cg.shared.global [%0], [%1], 16;\n" :: "r"(s), "l"(gmem));
}
#define CP_COMMIT() asm volatile("cp.async.commit_group;\n" ::: "memory")
#define CP_WAIT(n)  asm volatile("cp.async.wait_group %0;\n" :: "n"(n) : "memory")

#define MMA_F16(c, a, b)                                                        \
    asm volatile(                                                               \
        "mma.sync.aligned.m16n8k16.row.col.f32.f16.f16.f32 "                    \
        "{%0,%1,%2,%3},{%4,%5,%6,%7},{%8,%9},{%0,%1,%2,%3};\n"                  \
        : "+f"((c)[0]), "+f"((c)[1]), "+f"((c)[2]), "+f"((c)[3])                \
        : "r"((a)[0]), "r"((a)[1]), "r"((a)[2]), "r"((a)[3]),                   \
          "r"((b)[0]), "r"((b)[1]))

__device__ __forceinline__ void ldsm_x4(uint32_t& r0, uint32_t& r1, uint32_t& r2,
                                        uint32_t& r3, uint32_t saddr) {
    asm volatile("ldmatrix.sync.aligned.m8n8.x4.shared.b16 {%0,%1,%2,%3}, [%4];"
                 : "=r"(r0), "=r"(r1), "=r"(r2), "=r"(r3) : "r"(saddr));
}
__device__ __forceinline__ void ldsm_x4_t(uint32_t& r0, uint32_t& r1, uint32_t& r2,
                                          uint32_t& r3, uint32_t saddr) {
    asm volatile("ldmatrix.sync.aligned.m8n8.x4.trans.shared.b16 {%0,%1,%2,%3}, [%4];"
                 : "=r"(r0), "=r"(r1), "=r"(r2), "=r"(r3) : "r"(saddr));
}

// ---------------------------------------------------------------------------
// Fused prologue: convert_X | transpose_W | init_M in one launch.
// ---------------------------------------------------------------------------
__global__ __launch_bounds__(256) void prep_kernel(const float* __restrict__ x,
                                                   const float* __restrict__ w) {
    __shared__ float tile[64][33];   // used by transpose_W branch only
    int blk = (int)blockIdx.x;
    int tid = (int)threadIdx.x;

    if (blk < PREP_CVT) {
        int idx = blk * 256 + tid;
        int r = idx >> 8;
        int n0 = (idx & 255) * 4;
        float4 fa = *(const float4*)&x[r * NG + n0];
        float4 fb = *(const float4*)&x[r * NG + (NG - 4 - n0)];
        float a[4] = {fa.x, fa.y, fa.z, fa.w};
        float b[4] = {fb.w, fb.z, fb.y, fb.x};
        union { __half h[4]; uint2 u; } pe, pd;
#pragma unroll
        for (int i = 0; i < 4; i++) {
            pe.h[i] = __float2half(a[i] + b[i]);
            pd.h[i] = __float2half(a[i] - b[i]);
        }
        *(uint2*)&g_Xe[r * NH + n0] = pe.u;
        *(uint2*)&g_Xd[r * NH + n0] = pd.u;
    } else if (blk < PREP_TRW) {
        int b2 = blk - PREP_CVT;
        int kBase = (b2 & 7) * 64;
        int rBase = (b2 >> 3) * 32;
#pragma unroll
        for (int l = 0; l < 2; l++) {
            int idx = tid + l * 256;
            int r = idx >> 4;
            int q = idx & 15;
            float4 v = *(const float4*)&w[(rBase + r) * MODES + kBase + q * 4];
            tile[q * 4 + 0][r] = v.x;
            tile[q * 4 + 1][r] = v.y;
            tile[q * 4 + 2][r] = v.z;
            tile[q * 4 + 3][r] = v.w;
        }
        __syncthreads();
        {
            int kk = tid >> 2;
            int seg = (tid & 3) * 8;
            int k = kBase + kk;
            int pk = (k & 1) * MH + (k >> 1);
            union { __half h[8]; uint4 u; } pkt;
#pragma unroll
            for (int c = 0; c < 8; c++) pkt.h[c] = __float2half(tile[kk][seg + c]);
            *(uint4*)&g_Wt16[pk * RROWS + rBase + seg] = pkt.u;
        }
    } else {
        int idx = (blk - PREP_TRW) * 256 + tid;
        int k2 = idx >> 10, n = idx & (NH - 1);
        int ke = 2 * k2, ko = 2 * k2 + 1;
        const float inv = 1.0f / (float)(NG - 1);
        float ve = cospif((float)((ke * n) % (2 * (NG - 1))) * inv);
        float vo = cospif((float)((ko * n) % (2 * (NG - 1))) * inv);
        float cn = (n == 0) ? 1.0f : 2.0f;
        g_B1e[idx] = __float2half(ve * cn);
        g_B1o[idx] = __float2half(vo * cn);
        float cke = (ke == 0) ? 1.0f : 2.0f;
        g_B3e[n * MH + k2] = __float2half(ve * cke);
        g_B3o[n * MH + k2] = __float2half(vo * 2.0f);
    }
}

// ---------------------------------------------------------------------------
// GEMM1 (folded): C1h[p*256+bn+kc][r] = sum_{n<1024} A_p[r][n] * B_p[k][n]
//   CTA 128m x 64n, BK=64, 3-stage cp.async, one sync per iter.
// ---------------------------------------------------------------------------
extern __shared__ __align__(16) unsigned char dsm[];

__global__ __launch_bounds__(256, 2) void gemm1_mma() {
    int tid = (int)threadIdx.x;
    int bm = blockIdx.y * 128;   // r
    int bn = blockIdx.x * 64;    // k2 within parity
    int p  = blockIdx.z;
    const __half* Asrc = p ? g_Xd : g_Xe;
    const __half* Bsrc = p ? g_B1o : g_B1e;

    int warp = tid >> 5, lane = tid & 31;
    int wm = warp >> 2, wn = warp & 3;
    int g = lane >> 2, t2 = (lane & 3) * 2;

    uint32_t sbase = (uint32_t)__cvta_generic_to_shared(dsm);

    // A: 128 rows x 8 uint4/row = 1024 (4/thread); B: 64 rows x 8 = 512 (2/thread)
    uint32_t aoff[4];
#pragma unroll
    for (int mi = 0; mi < 4; mi++)
        aoff[mi] = ((wm * 64 + mi * 16 + (lane & 15)) * SLD1 + ((lane >> 4) << 3)) * 2;
    uint32_t boff = (uint32_t)(128 * SLD1 * 2) +
                    ((wn * 16 + (lane & 7) + ((lane >> 4) << 3)) * SLD1 +
                     (((lane >> 3) & 1) << 3)) * 2;

    float acc[4][2][4];
#pragma unroll
    for (int a = 0; a < 4; a++)
#pragma unroll
        for (int b = 0; b < 2; b++)
#pragma unroll
            for (int c = 0; c < 4; c++) acc[a][b][c] = 0.0f;

    const int NIT = NH / 64;   // 16

#define G1_LOAD(st)                                                                  \
    do {                                                                             \
        __half* sA = (__half*)(dsm + ((st) % 3) * STG_B);                            \
        __half* sB = sA + 128 * SLD1;                                                \
        int k0 = (st) * 64;                                                          \
        _Pragma("unroll")                                                            \
        for (int l = 0; l < 4; l++) {                                                \
            int idx = tid + l * 256;                                                 \
            int row = idx >> 3, seg = (idx & 7) * 8;                                 \
            cp_async16(&sA[row * SLD1 + seg], &Asrc[(bm + row) * NH + k0 + seg]);    \
        }                                                                            \
        _Pragma("unroll")                                                            \
        for (int l = 0; l < 2; l++) {                                                \
            int idx = tid + l * 256;                                                 \
            int row = idx >> 3, seg = (idx & 7) * 8;                                 \
            cp_async16(&sB[row * SLD1 + seg], &Bsrc[(bn + row) * NH + k0 + seg]);    \
        }                                                                            \
        CP_COMMIT();                                                                 \
    } while (0)

    G1_LOAD(0);
    G1_LOAD(1);

    for (int it = 0; it < NIT; it++) {
        CP_WAIT(1);
        __syncthreads();
        if (it + 2 < NIT) G1_LOAD(it + 2);
        uint32_t stg = sbase + (uint32_t)((it % 3) * STG_B);
#pragma unroll
        for (int ks = 0; ks < 4; ks++) {
            uint32_t kb = (uint32_t)(ks * 32);   // 16 halves
            uint32_t a[4][4], b[2][2];
#pragma unroll
            for (int mi = 0; mi < 4; mi++)
                ldsm_x4(a[mi][0], a[mi][1], a[mi][2], a[mi][3], stg + aoff[mi] + kb);
            ldsm_x4(b[0][0], b[0][1], b[1][0], b[1][1], stg + boff + kb);
#pragma unroll
            for (int mi = 0; mi < 4; mi++)
#pragma unroll
                for (int ni = 0; ni < 2; ni++)
                    MMA_F16(acc[mi][ni], a[mi], b[ni]);
        }
    }
    __syncthreads();

    // Epilogue: stage transposed fp16 cbuf[k][r], coalesced write C1h (parity-major).
    __half* cbuf = (__half*)dsm;
#pragma unroll
    for (int mi = 0; mi < 4; mi++)
#pragma unroll
        for (int ni = 0; ni < 2; ni++) {
            int rl = wm * 64 + mi * 16 + g;
            int cl = wn * 16 + ni * 8 + t2;
            cbuf[cl * SLDE + rl]           = __float2half(acc[mi][ni][0]);
            cbuf[(cl + 1) * SLDE + rl]     = __float2half(acc[mi][ni][1]);
            cbuf[cl * SLDE + rl + 8]       = __float2half(acc[mi][ni][2]);
            cbuf[(cl + 1) * SLDE + rl + 8] = __float2half(acc[mi][ni][3]);
        }
    __syncthreads();
    int kgBase = p * MH + bn;
#pragma unroll
    for (int q = 0; q < 8; q++) {
        int idx = tid + q * 256;
        int kc = idx >> 5;
        int seg = (idx & 31) * 4;
        *(uint2*)&g_C1h[(kgBase + kc) * RROWS + bm + seg] = *(uint2*)&cbuf[kc * SLDE + seg];
    }
}

// ---------------------------------------------------------------------------
// Mix (tensor cores): per pk, C2h[pk][b*64+o] = sum_i C1h[pk][b*64+i]*Wt16[pk][i][o]
// ---------------------------------------------------------------------------
__global__ __launch_bounds__(128) void mix_mma_kernel() {
    int k = blockIdx.x;
    __shared__ __align__(16) __half sA[64][72];
    __shared__ __align__(16) __half sW[64][72];
    const __half* a = &g_C1h[k * RROWS];
    const __half* w = &g_Wt16[k * RROWS];
    int tid = (int)threadIdx.x;
#pragma unroll
    for (int l = 0; l < 4; l++) {
        int idx = tid + l * 128;
        int r = idx >> 3, seg = (idx & 7) * 8;
        *(uint4*)&sA[r][seg] = *(const uint4*)&a[r * 64 + seg];
        *(uint4*)&sW[r][seg] = *(const uint4*)&w[r * 64 + seg];
    }
    __syncthreads();

    int warp = tid >> 5, lane = tid & 31;
    int g = lane >> 2, t2 = (lane & 3) * 2;
    uint32_t sAb = (uint32_t)__cvta_generic_to_shared(&sA[0][0]);
    uint32_t sWb = (uint32_t)__cvta_generic_to_shared(&sW[0][0]);

    float acc[8][4];
#pragma unroll
    for (int i = 0; i < 8; i++)
#pragma unroll
        for (int j = 0; j < 4; j++) acc[i][j] = 0.0f;

#pragma unroll
    for (int ks = 0; ks < 4; ks++) {
        uint32_t av[4];
        uint32_t aaddr = sAb + ((warp * 16 + (lane & 15)) * 72 + ks * 16 + ((lane >> 4) << 3)) * 2;
        ldsm_x4(av[0], av[1], av[2], av[3], aaddr);
#pragma unroll
        for (int nq = 0; nq < 4; nq++) {
            uint32_t b0, b1, b2, b3;
            uint32_t baddr = sWb + ((ks * 16 + (lane & 15)) * 72 + nq * 16 + ((lane >> 4) << 3)) * 2;
            ldsm_x4_t(b0, b1, b2, b3, baddr);
            uint32_t bb0[2] = {b0, b1}, bb1[2] = {b2, b3};
            MMA_F16(acc[nq * 2], av, bb0);
            MMA_F16(acc[nq * 2 + 1], av, bb1);
        }
    }

    __half* c2 = &g_C2h[k * RROWS];
#pragma unroll
    for (int ni = 0; ni < 8; ni++) {
        int col = ni * 8 + t2;
        __half2 v0 = __floats2half2_rn(acc[ni][0], acc[ni][1]);
        __half2 v1 = __floats2half2_rn(acc[ni][2], acc[ni][3]);
        *(__half2*)&c2[(warp * 16 + g) * 64 + col]     = v0;
        *(__half2*)&c2[(warp * 16 + g + 8) * 64 + col] = v1;
    }
}

// ---------------------------------------------------------------------------
// GEMM3 (folded + butterfly), A direct from C2h[pk][r] via ldmatrix.trans.
//   CTA 128m x 64n, BK=64, 3-stage, one sync per iter; 8 iters (4 even + 4 odd).
// ---------------------------------------------------------------------------
__global__ __launch_bounds__(256, 2) void gemm3_mma(float* __restrict__ out) {
    int tid = (int)threadIdx.x;
    int bm = blockIdx.y * 128;   // r
    int bn = blockIdx.x * 64;    // n (folded half)
    int warp = tid >> 5, lane = tid & 31;
    int wm = warp >> 2, wn = warp & 3;
    int g = lane >> 2, t2 = (lane & 3) * 2;

    uint32_t sbase = (uint32_t)__cvta_generic_to_shared(dsm);

    uint32_t atoff[4];
#pragma unroll
    for (int mi = 0; mi < 4; mi++)
        atoff[mi] = (((((lane >> 4) & 1) * 8 + (lane & 7)) * SLDA) +
                     wm * 64 + mi * 16 + (((lane >> 3) & 1) * 8)) * 2;
    uint32_t boff = (uint32_t)(64 * SLDA * 2) +
                    ((wn * 16 + (lane & 7) + ((lane >> 4) << 3)) * SLD1 +
                     (((lane >> 3) & 1) << 3)) * 2;

    float acc_e[4][2][4], acc_o[4][2][4];
#pragma unroll
    for (int a = 0; a < 4; a++)
#pragma unroll
        for (int b = 0; b < 2; b++)
#pragma unroll
            for (int c = 0; c < 4; c++) { acc_e[a][b][c] = 0.0f; acc_o[a][b][c] = 0.0f; }

    // iteration j in [0,8): phase = j>>2, kk = (j&3)*64
#define G3_LOAD(j)                                                                   \
    do {                                                                             \
        int s_ = (j) % 3;                                                            \
        int ph_ = (j) >> 2;                                                          \
        int kk_ = ((j) & 3) * 64;                                                    \
        __half* sA_ = (__half*)(dsm + s_ * STG3_B);                                  \
        __half* sB_ = (__half*)(dsm + s_ * STG3_B + 64 * SLDA * 2);                  \
        const __half* Bs_ = ph_ ? g_B3o : g_B3e;                                     \
        _Pragma("unroll")                                                            \
        for (int l_ = 0; l_ < 4; l_++) {                                             \
            int idx_ = tid + l_ * 256;                                               \
            int row_ = idx_ >> 4, seg_ = (idx_ & 15) * 8;                            \
            cp_async16(&sA_[row_ * SLDA + seg_],                                     \
                       &g_C2h[(ph_ * MH + kk_ + row_) * RROWS + bm + seg_]);         \
        }                                                                            \
        _Pragma("unroll")                                                            \
        for (int l_ = 0; l_ < 2; l_++) {                                             \
            int idx_ = tid + l_ * 256;                                               \
            int row_ = idx_ >> 3, seg_ = (idx_ & 7) * 8;                             \
            cp_async16(&sB_[row_ * SLD1 + seg_], &Bs_[(bn + row_) * MH + kk_ + seg_]); \
        }                                                                            \
        CP_COMMIT();                                                                 \
    } while (0)

#define G3_COMPUTE(j, ACC)                                                           \
    do {                                                                             \
        uint32_t stg_ = sbase + (uint32_t)(((j) % 3) * STG3_B);                      \
        _Pragma("unroll")                                                            \
        for (int ks_ = 0; ks_ < 4; ks_++) {                                          \
            uint32_t ka_ = (uint32_t)(ks_ * 16 * SLDA * 2);                          \
            uint32_t kb_ = (uint32_t)(ks_ * 32);                                     \
            uint32_t a_[4][4], b_[2][2];                                             \
            _Pragma("unroll")                                                        \
            for (int mi_ = 0; mi_ < 4; mi_++)                                        \
                ldsm_x4_t(a_[mi_][0], a_[mi_][1], a_[mi_][2], a_[mi_][3],            \
                          stg_ + atoff[mi_] + ka_);                                  \
            ldsm_x4(b_[0][0], b_[0][1], b_[1][0], b_[1][1], stg_ + boff + kb_);      \
            _Pragma("unroll")                                                        \
            for (int mi_ = 0; mi_ < 4; mi_++)                                        \
                _Pragma("unroll")                                                    \
                for (int ni_ = 0; ni_ < 2; ni_++)                                    \
                    MMA_F16(ACC[mi_][ni_], a_[mi_], b_[ni_]);                        \
        }                                                                            \
    } while (0)

    G3_LOAD(0);
    G3_LOAD(1);

    for (int j = 0; j < 4; j++) {
        CP_WAIT(1);
        __syncthreads();
        if (j + 2 < 8) G3_LOAD(j + 2);
        G3_COMPUTE(j, acc_e);
    }
    for (int j = 4; j < 8; j++) {
        CP_WAIT(1);
        __syncthreads();
        if (j + 2 < 8) G3_LOAD(j + 2);
        G3_COMPUTE(j, acc_o);
    }

    // Butterfly epilogue: out[r][n] = e+o, out[r][2047-n] = e-o
#pragma unroll
    for (int mi = 0; mi < 4; mi++)
#pragma unroll
        for (int ni = 0; ni < 2; ni++) {
            int row = bm + wm * 64 + mi * 16 + g;
            int col = bn + wn * 16 + ni * 8 + t2;
            float e0 = acc_e[mi][ni][0], e1 = acc_e[mi][ni][1];
            float e2 = acc_e[mi][ni][2], e3 = acc_e[mi][ni][3];
            float o0 = acc_o[mi][ni][0], o1 = acc_o[mi][ni][1];
            float o2 = acc_o[mi][ni][2], o3 = acc_o[mi][ni][3];
            *(float2*)&out[row * NG + col]       = make_float2(e0 + o0, e1 + o1);
            *(float2*)&out[(row + 8) * NG + col] = make_float2(e2 + o2, e3 + o3);
            int mcol = NG - 2 - col;
            *(float2*)&out[row * NG + mcol]       = make_float2(e1 - o1, e0 - o0);
            *(float2*)&out[(row + 8) * NG + mcol] = make_float2(e3 - o3, e2 - o2);
        }
}

// ---------------------------------------------------------------------------
// Launch
// ---------------------------------------------------------------------------
extern "C" void kernel_launch(void* const* d_in, const int* in_sizes, int n_in,
                              void* d_out, int out_size) {
    const float* x = (const float*)d_in[0];   // [64, 64, 2048] f32
    const float* w = (const float*)d_in[1];   // [64, 64, 512]  f32
    float* out = (float*)d_out;               // [64, 64, 2048] f32

    cudaFuncSetAttribute(gemm1_mma, cudaFuncAttributeMaxDynamicSharedMemorySize, NSTG * STG_B);
    cudaFuncSetAttribute(gemm3_mma, cudaFuncAttributeMaxDynamicSharedMemorySize, NSTG * STG3_B);

    prep_kernel<<<PREP_TOT, 256>>>(x, w);
    gemm1_mma<<<dim3(MH / 64, RROWS / 128, 2), 256, NSTG * STG_B>>>();
    mix_mma_kernel<<<MODES, 128>>>();
    gemm3_mma<<<dim3(NH / 64, RROWS / 128), 256, NSTG * STG3_B>>>(out);
}

// round 12
// speedup vs baseline: 1.3023x; 1.1032x over previous
#include <cuda_runtime.h>
#include <cuda_fp16.h>
#include <stdint.h>

#define NG      2048
#define NH      1024          // folded grid length
#define MODES   512
#define MH      256           // modes per parity
#define RROWS   4096
#define SLD1    72            // [r][k]/[n][k] smem row stride for BK=64 (halves)
#define SLDA    136           // gemm3 A-tile row stride (half), [k][r] layout
#define SLDE    136           // epilogue cbuf stride (half)
#define STG_B   ((128 + 128) * SLD1 * 2)          // gemm1 stage bytes: 36864
#define STG3_B  (64 * SLDA * 2 + 128 * SLD1 * 2)  // gemm3 stage bytes: 35840
#define NSTG    3

// prep_kernel block ranges
#define PREP_CVT   4096                       // convert_X blocks
#define PREP_TRW   (PREP_CVT + 1024)          // transpose_W blocks
#define PREP_TOT   (PREP_TRW + 1024)          // init_M blocks

// ---------------------------------------------------------------------------
// Static device scratch
// ---------------------------------------------------------------------------
__device__ __align__(16) __half g_B1e[MH * NH];        // [k2][n]  even fwd op, c[n] folded
__device__ __align__(16) __half g_B1o[MH * NH];        // [k2][n]  odd  fwd op
__device__ __align__(16) __half g_B3e[NH * MH];        // [n][k2]  even inv op, c[k] folded
__device__ __align__(16) __half g_B3o[NH * MH];        // [n][k2]  odd  inv op
__device__ __align__(16) __half g_Xe[RROWS * NH];      // [r][n]  x[n]+x[2047-n]
__device__ __align__(16) __half g_Xd[RROWS * NH];      // [r][n]  x[n]-x[2047-n]
__device__ __align__(16) __half g_C1h[MODES * RROWS];  // [pk][r] parity-major modes
__device__ __align__(16) __half g_Wt16[MODES * RROWS]; // [pk][i*64+o] parity-major
__device__ __align__(16) __half g_C2h[MODES * RROWS];  // [pk][r]

// ---------------------------------------------------------------------------
// Async-copy / MMA / ldmatrix helpers
// ---------------------------------------------------------------------------
__device__ __forceinline__ void cp_async16(void* smem, const void* gmem) {
    uint32_t s = (uint32_t)__cvta_generic_to_shared(smem);
    asm volatile("cp.async.cg.shared.global [%0], [%1], 16;\n" :: "r"(s), "l"(gmem));
}
#define CP_COMMIT() asm volatile("cp.async.commit_group;\n" ::: "memory")
#define CP_WAIT(n)  asm volatile("cp.async.wait_group %0;\n" :: "n"(n) : "memory")

#define MMA_F16(c, a, b)                                                        \
    asm volatile(                                                               \
        "mma.sync.aligned.m16n8k16.row.col.f32.f16.f16.f32 "                    \
        "{%0,%1,%2,%3},{%4,%5,%6,%7},{%8,%9},{%0,%1,%2,%3};\n"                  \
        : "+f"((c)[0]), "+f"((c)[1]), "+f"((c)[2]), "+f"((c)[3])                \
        : "r"((a)[0]), "r"((a)[1]), "r"((a)[2]), "r"((a)[3]),                   \
          "r"((b)[0]), "r"((b)[1]))

__device__ __forceinline__ void ldsm_x4(uint32_t& r0, uint32_t& r1, uint32_t& r2,
                                        uint32_t& r3, uint32_t saddr) {
    asm volatile("ldmatrix.sync.aligned.m8n8.x4.shared.b16 {%0,%1,%2,%3}, [%4];"
                 : "=r"(r0), "=r"(r1), "=r"(r2), "=r"(r3) : "r"(saddr));
}
__device__ __forceinline__ void ldsm_x4_t(uint32_t& r0, uint32_t& r1, uint32_t& r2,
                                          uint32_t& r3, uint32_t saddr) {
    asm volatile("ldmatrix.sync.aligned.m8n8.x4.trans.shared.b16 {%0,%1,%2,%3}, [%4];"
                 : "=r"(r0), "=r"(r1), "=r"(r2), "=r"(r3) : "r"(saddr));
}

// ---------------------------------------------------------------------------
// Fused prologue: convert_X | transpose_W | init_M in one launch.
// ---------------------------------------------------------------------------
__global__ __launch_bounds__(256) void prep_kernel(const float* __restrict__ x,
                                                   const float* __restrict__ w) {
    __shared__ float tile[64][33];   // used by transpose_W branch only
    int blk = (int)blockIdx.x;
    int tid = (int)threadIdx.x;

    if (blk < PREP_CVT) {
        int idx = blk * 256 + tid;
        int r = idx >> 8;
        int n0 = (idx & 255) * 4;
        float4 fa = *(const float4*)&x[r * NG + n0];
        float4 fb = *(const float4*)&x[r * NG + (NG - 4 - n0)];
        float a[4] = {fa.x, fa.y, fa.z, fa.w};
        float b[4] = {fb.w, fb.z, fb.y, fb.x};
        union { __half h[4]; uint2 u; } pe, pd;
#pragma unroll
        for (int i = 0; i < 4; i++) {
            pe.h[i] = __float2half(a[i] + b[i]);
            pd.h[i] = __float2half(a[i] - b[i]);
        }
        *(uint2*)&g_Xe[r * NH + n0] = pe.u;
        *(uint2*)&g_Xd[r * NH + n0] = pd.u;
    } else if (blk < PREP_TRW) {
        int b2 = blk - PREP_CVT;
        int kBase = (b2 & 7) * 64;
        int rBase = (b2 >> 3) * 32;
#pragma unroll
        for (int l = 0; l < 2; l++) {
            int idx = tid + l * 256;
            int r = idx >> 4;
            int q = idx & 15;
            float4 v = *(const float4*)&w[(rBase + r) * MODES + kBase + q * 4];
            tile[q * 4 + 0][r] = v.x;
            tile[q * 4 + 1][r] = v.y;
            tile[q * 4 + 2][r] = v.z;
            tile[q * 4 + 3][r] = v.w;
        }
        __syncthreads();
        {
            int kk = tid >> 2;
            int seg = (tid & 3) * 8;
            int k = kBase + kk;
            int pk = (k & 1) * MH + (k >> 1);
            union { __half h[8]; uint4 u; } pkt;
#pragma unroll
            for (int c = 0; c < 8; c++) pkt.h[c] = __float2half(tile[kk][seg + c]);
            *(uint4*)&g_Wt16[pk * RROWS + rBase + seg] = pkt.u;
        }
    } else {
        int idx = (blk - PREP_TRW) * 256 + tid;
        int k2 = idx >> 10, n = idx & (NH - 1);
        int ke = 2 * k2, ko = 2 * k2 + 1;
        const float inv = 1.0f / (float)(NG - 1);
        float ve = cospif((float)((ke * n) % (2 * (NG - 1))) * inv);
        float vo = cospif((float)((ko * n) % (2 * (NG - 1))) * inv);
        float cn = (n == 0) ? 1.0f : 2.0f;
        g_B1e[idx] = __float2half(ve * cn);
        g_B1o[idx] = __float2half(vo * cn);
        float cke = (ke == 0) ? 1.0f : 2.0f;
        g_B3e[n * MH + k2] = __float2half(ve * cke);
        g_B3o[n * MH + k2] = __float2half(vo * 2.0f);
    }
}

// ---------------------------------------------------------------------------
// GEMM1 (folded): C1h[p*256+bn+kc][r] = sum_{n<1024} A_p[r][n] * B_p[k][n]
//   CTA 128m x 128n, 8 warps 2m x 4n (warp 64x32), BK=64, 3-stage cp.async.
// ---------------------------------------------------------------------------
extern __shared__ __align__(16) unsigned char dsm[];

__global__ __launch_bounds__(256, 2) void gemm1_mma() {
    int tid = (int)threadIdx.x;
    int bm = blockIdx.y * 128;   // r
    int bn = blockIdx.x * 128;   // k2 within parity
    int p  = blockIdx.z;
    const __half* Asrc = p ? g_Xd : g_Xe;
    const __half* Bsrc = p ? g_B1o : g_B1e;

    int warp = tid >> 5, lane = tid & 31;
    int wm = warp >> 2, wn = warp & 3;
    int g = lane >> 2, t2 = (lane & 3) * 2;

    uint32_t sbase = (uint32_t)__cvta_generic_to_shared(dsm);

    uint32_t aoff[4];
#pragma unroll
    for (int mi = 0; mi < 4; mi++)
        aoff[mi] = ((wm * 64 + mi * 16 + (lane & 15)) * SLD1 + ((lane >> 4) << 3)) * 2;
    uint32_t boff[2];
#pragma unroll
    for (int nq = 0; nq < 2; nq++)
        boff[nq] = (uint32_t)(128 * SLD1 * 2) +
                   ((wn * 32 + nq * 16 + (lane & 7) + ((lane >> 4) << 3)) * SLD1 +
                    (((lane >> 3) & 1) << 3)) * 2;

    float acc[4][4][4];
#pragma unroll
    for (int a = 0; a < 4; a++)
#pragma unroll
        for (int b = 0; b < 4; b++)
#pragma unroll
            for (int c = 0; c < 4; c++) acc[a][b][c] = 0.0f;

    const int NIT = NH / 64;   // 16

#define G1_LOAD(st)                                                                  \
    do {                                                                             \
        __half* sA = (__half*)(dsm + ((st) % 3) * STG_B);                            \
        __half* sB = sA + 128 * SLD1;                                                \
        int k0 = (st) * 64;                                                          \
        _Pragma("unroll")                                                            \
        for (int l = 0; l < 4; l++) {                                                \
            int idx = tid + l * 256;                                                 \
            int row = idx >> 3, seg = (idx & 7) * 8;                                 \
            cp_async16(&sA[row * SLD1 + seg], &Asrc[(bm + row) * NH + k0 + seg]);    \
        }                                                                            \
        _Pragma("unroll")                                                            \
        for (int l = 0; l < 4; l++) {                                                \
            int idx = tid + l * 256;                                                 \
            int row = idx >> 3, seg = (idx & 7) * 8;                                 \
            cp_async16(&sB[row * SLD1 + seg], &Bsrc[(bn + row) * NH + k0 + seg]);    \
        }                                                                            \
        CP_COMMIT();                                                                 \
    } while (0)

    G1_LOAD(0);
    G1_LOAD(1);

    for (int it = 0; it < NIT; it++) {
        CP_WAIT(1);
        __syncthreads();
        if (it + 2 < NIT) G1_LOAD(it + 2);
        uint32_t stg = sbase + (uint32_t)((it % 3) * STG_B);
#pragma unroll
        for (int ks = 0; ks < 4; ks++) {
            uint32_t kb = (uint32_t)(ks * 32);   // 16 halves
            uint32_t a[4][4], b[4][2];
#pragma unroll
            for (int mi = 0; mi < 4; mi++)
                ldsm_x4(a[mi][0], a[mi][1], a[mi][2], a[mi][3], stg + aoff[mi] + kb);
#pragma unroll
            for (int nq = 0; nq < 2; nq++)
                ldsm_x4(b[nq * 2][0], b[nq * 2][1], b[nq * 2 + 1][0], b[nq * 2 + 1][1],
                        stg + boff[nq] + kb);
#pragma unroll
            for (int mi = 0; mi < 4; mi++)
#pragma unroll
                for (int ni = 0; ni < 4; ni++)
                    MMA_F16(acc[mi][ni], a[mi], b[ni]);
        }
    }
    __syncthreads();

    // Epilogue: stage transposed fp16 cbuf[k][r] (128x128), coalesced write C1h.
    __half* cbuf = (__half*)dsm;   // 128 x SLDE halves = 34816 B
#pragma unroll
    for (int mi = 0; mi < 4; mi++)
#pragma unroll
        for (int ni = 0; ni < 4; ni++) {
            int rl = wm * 64 + mi * 16 + g;
            int cl = wn * 32 + ni * 8 + t2;
            cbuf[cl * SLDE + rl]           = __float2half(acc[mi][ni][0]);
            cbuf[(cl + 1) * SLDE + rl]     = __float2half(acc[mi][ni][1]);
            cbuf[cl * SLDE + rl + 8]       = __float2half(acc[mi][ni][2]);
            cbuf[(cl + 1) * SLDE + rl + 8] = __float2half(acc[mi][ni][3]);
        }
    __syncthreads();
    int kgBase = p * MH + bn;
#pragma unroll
    for (int q = 0; q < 8; q++) {
        int idx = tid + q * 256;               // 2048 uint4 = 128k x 16 segs
        int kc = idx >> 4;
        int seg = (idx & 15) * 8;
        *(uint4*)&g_C1h[(kgBase + kc) * RROWS + bm + seg] = *(uint4*)&cbuf[kc * SLDE + seg];
    }
}

// ---------------------------------------------------------------------------
// Mix (tensor cores): per pk, C2h[pk][b*64+o] = sum_i C1h[pk][b*64+i]*Wt16[pk][i][o]
// ---------------------------------------------------------------------------
__global__ __launch_bounds__(128) void mix_mma_kernel() {
    int k = blockIdx.x;
    __shared__ __align__(16) __half sA[64][72];
    __shared__ __align__(16) __half sW[64][72];
    const __half* a = &g_C1h[k * RROWS];
    const __half* w = &g_Wt16[k * RROWS];
    int tid = (int)threadIdx.x;
#pragma unroll
    for (int l = 0; l < 4; l++) {
        int idx = tid + l * 128;
        int r = idx >> 3, seg = (idx & 7) * 8;
        *(uint4*)&sA[r][seg] = *(const uint4*)&a[r * 64 + seg];
        *(uint4*)&sW[r][seg] = *(const uint4*)&w[r * 64 + seg];
    }
    __syncthreads();

    int warp = tid >> 5, lane = tid & 31;
    int g = lane >> 2, t2 = (lane & 3) * 2;
    uint32_t sAb = (uint32_t)__cvta_generic_to_shared(&sA[0][0]);
    uint32_t sWb = (uint32_t)__cvta_generic_to_shared(&sW[0][0]);

    float acc[8][4];
#pragma unroll
    for (int i = 0; i < 8; i++)
#pragma unroll
        for (int j = 0; j < 4; j++) acc[i][j] = 0.0f;

#pragma unroll
    for (int ks = 0; ks < 4; ks++) {
        uint32_t av[4];
        uint32_t aaddr = sAb + ((warp * 16 + (lane & 15)) * 72 + ks * 16 + ((lane >> 4) << 3)) * 2;
        ldsm_x4(av[0], av[1], av[2], av[3], aaddr);
#pragma unroll
        for (int nq = 0; nq < 4; nq++) {
            uint32_t b0, b1, b2, b3;
            uint32_t baddr = sWb + ((ks * 16 + (lane & 15)) * 72 + nq * 16 + ((lane >> 4) << 3)) * 2;
            ldsm_x4_t(b0, b1, b2, b3, baddr);
            uint32_t bb0[2] = {b0, b1}, bb1[2] = {b2, b3};
            MMA_F16(acc[nq * 2], av, bb0);
            MMA_F16(acc[nq * 2 + 1], av, bb1);
        }
    }

    __half* c2 = &g_C2h[k * RROWS];
#pragma unroll
    for (int ni = 0; ni < 8; ni++) {
        int col = ni * 8 + t2;
        __half2 v0 = __floats2half2_rn(acc[ni][0], acc[ni][1]);
        __half2 v1 = __floats2half2_rn(acc[ni][2], acc[ni][3]);
        *(__half2*)&c2[(warp * 16 + g) * 64 + col]     = v0;
        *(__half2*)&c2[(warp * 16 + g + 8) * 64 + col] = v1;
    }
}

// ---------------------------------------------------------------------------
// GEMM3 (folded + butterfly), A direct from C2h[pk][r] via ldmatrix.trans.
//   CTA 128m x 128n, 8 warps 2m x 4n (warp 64x32), BK=64, 3-stage, dual e/o acc.
// ---------------------------------------------------------------------------
__global__ __launch_bounds__(256, 1) void gemm3_mma(float* __restrict__ out) {
    int tid = (int)threadIdx.x;
    int bm = blockIdx.y * 128;   // r
    int bn = blockIdx.x * 128;   // n (folded half)
    int warp = tid >> 5, lane = tid & 31;
    int wm = warp >> 2, wn = warp & 3;
    int g = lane >> 2, t2 = (lane & 3) * 2;

    uint32_t sbase = (uint32_t)__cvta_generic_to_shared(dsm);

    uint32_t atoff[4];
#pragma unroll
    for (int mi = 0; mi < 4; mi++)
        atoff[mi] = (((((lane >> 4) & 1) * 8 + (lane & 7)) * SLDA) +
                     wm * 64 + mi * 16 + (((lane >> 3) & 1) * 8)) * 2;
    uint32_t boff[2];
#pragma unroll
    for (int nq = 0; nq < 2; nq++)
        boff[nq] = (uint32_t)(64 * SLDA * 2) +
                   ((wn * 32 + nq * 16 + (lane & 7) + ((lane >> 4) << 3)) * SLD1 +
                    (((lane >> 3) & 1) << 3)) * 2;

    float acc_e[4][4][4], acc_o[4][4][4];
#pragma unroll
    for (int a = 0; a < 4; a++)
#pragma unroll
        for (int b = 0; b < 4; b++)
#pragma unroll
            for (int c = 0; c < 4; c++) { acc_e[a][b][c] = 0.0f; acc_o[a][b][c] = 0.0f; }

    // iteration j in [0,8): phase = j>>2, kk = (j&3)*64
#define G3_LOAD(j)                                                                   \
    do {                                                                             \
        int s_ = (j) % 3;                                                            \
        int ph_ = (j) >> 2;                                                          \
        int kk_ = ((j) & 3) * 64;                                                    \
        __half* sA_ = (__half*)(dsm + s_ * STG3_B);                                  \
        __half* sB_ = (__half*)(dsm + s_ * STG3_B + 64 * SLDA * 2);                  \
        const __half* Bs_ = ph_ ? g_B3o : g_B3e;                                     \
        _Pragma("unroll")                                                            \
        for (int l_ = 0; l_ < 4; l_++) {                                             \
            int idx_ = tid + l_ * 256;                                               \
            int row_ = idx_ >> 4, seg_ = (idx_ & 15) * 8;                            \
            cp_async16(&sA_[row_ * SLDA + seg_],                                     \
                       &g_C2h[(ph_ * MH + kk_ + row_) * RROWS + bm + seg_]);         \
        }                                                                            \
        _Pragma("unroll")                                                            \
        for (int l_ = 0; l_ < 4; l_++) {                                             \
            int idx_ = tid + l_ * 256;                                               \
            int row_ = idx_ >> 3, seg_ = (idx_ & 7) * 8;                             \
            cp_async16(&sB_[row_ * SLD1 + seg_], &Bs_[(bn + row_) * MH + kk_ + seg_]); \
        }                                                                            \
        CP_COMMIT();                                                                 \
    } while (0)

#define G3_COMPUTE(j, ACC)                                                           \
    do {                                                                             \
        uint32_t stg_ = sbase + (uint32_t)(((j) % 3) * STG3_B);                      \
        _Pragma("unroll")                                                            \
        for (int ks_ = 0; ks_ < 4; ks_++) {                                          \
            uint32_t ka_ = (uint32_t)(ks_ * 16 * SLDA * 2);                          \
            uint32_t kb_ = (uint32_t)(ks_ * 32);                                     \
            uint32_t a_[4][4], b_[4][2];                                             \
            _Pragma("unroll")                                                        \
            for (int mi_ = 0; mi_ < 4; mi_++)                                        \
                ldsm_x4_t(a_[mi_][0], a_[mi_][1], a_[mi_][2], a_[mi_][3],            \
                          stg_ + atoff[mi_] + ka_);                                  \
            _Pragma("unroll")                                                        \
            for (int nq_ = 0; nq_ < 2; nq_++)                                        \
                ldsm_x4(b_[nq_ * 2][0], b_[nq_ * 2][1],                              \
                        b_[nq_ * 2 + 1][0], b_[nq_ * 2 + 1][1],                      \
                        stg_ + boff[nq_] + kb_);                                     \
            _Pragma("unroll")                                                        \
            for (int mi_ = 0; mi_ < 4; mi_++)                                        \
                _Pragma("unroll")                                                    \
                for (int ni_ = 0; ni_ < 4; ni_++)                                    \
                    MMA_F16(ACC[mi_][ni_], a_[mi_], b_[ni_]);                        \
        }                                                                            \
    } while (0)

    G3_LOAD(0);
    G3_LOAD(1);

    for (int j = 0; j < 4; j++) {
        CP_WAIT(1);
        __syncthreads();
        if (j + 2 < 8) G3_LOAD(j + 2);
        G3_COMPUTE(j, acc_e);
    }
    for (int j = 4; j < 8; j++) {
        CP_WAIT(1);
        __syncthreads();
        if (j + 2 < 8) G3_LOAD(j + 2);
        G3_COMPUTE(j, acc_o);
    }

    // Butterfly epilogue: out[r][n] = e+o, out[r][2047-n] = e-o
#pragma unroll
    for (int mi = 0; mi < 4; mi++)
#pragma unroll
        for (int ni = 0; ni < 4; ni++) {
            int row = bm + wm * 64 + mi * 16 + g;
            int col = bn + wn * 32 + ni * 8 + t2;
            float e0 = acc_e[mi][ni][0], e1 = acc_e[mi][ni][1];
            float e2 = acc_e[mi][ni][2], e3 = acc_e[mi][ni][3];
            float o0 = acc_o[mi][ni][0], o1 = acc_o[mi][ni][1];
            float o2 = acc_o[mi][ni][2], o3 = acc_o[mi][ni][3];
            *(float2*)&out[row * NG + col]       = make_float2(e0 + o0, e1 + o1);
            *(float2*)&out[(row + 8) * NG + col] = make_float2(e2 + o2, e3 + o3);
            int mcol = NG - 2 - col;
            *(float2*)&out[row * NG + mcol]       = make_float2(e1 - o1, e0 - o0);
            *(float2*)&out[(row + 8) * NG + mcol] = make_float2(e3 - o3, e2 - o2);
        }
}

// ---------------------------------------------------------------------------
// Launch
// ---------------------------------------------------------------------------
extern "C" void kernel_launch(void* const* d_in, const int* in_sizes, int n_in,
                              void* d_out, int out_size) {
    const float* x = (const float*)d_in[0];   // [64, 64, 2048] f32
    const float* w = (const float*)d_in[1];   // [64, 64, 512]  f32
    float* out = (float*)d_out;               // [64, 64, 2048] f32

    cudaFuncSetAttribute(gemm1_mma, cudaFuncAttributeMaxDynamicSharedMemorySize, NSTG * STG_B);
    cudaFuncSetAttribute(gemm3_mma, cudaFuncAttributeMaxDynamicSharedMemorySize, NSTG * STG3_B);

    prep_kernel<<<PREP_TOT, 256>>>(x, w);
    gemm1_mma<<<dim3(MH / 128, RROWS / 128, 2), 256, NSTG * STG_B>>>();
    mix_mma_kernel<<<MODES, 128>>>();
    gemm3_mma<<<dim3(NH / 128, RROWS / 128), 256, NSTG * STG3_B>>>(out);
}